// round 1
// baseline (speedup 1.0000x reference)
#include <cuda_runtime.h>
#include <math.h>

#define Ng 96    // number of graphs (both S and T)
#define nS 48    // nodes per graph
#define RK 16    // low rank
#define Dd 128   // feature dim
#define Cc 10    // classes
#define LDX 132  // padded smem row stride (floats)

// ---------- persistent scratch (no allocations allowed) ----------
__device__ float g_d0S[Ng][nS];
__device__ float g_d0T[Ng][nS];
__device__ float g_w[Ng][nS];
__device__ float g_z[Ng][nS];
__device__ float g_KST[Ng * Ng];

// ============================================================
// Kernel A: per-graph precompute: d0 (layer-0 diag normalizer),
// w = V^T (VU)^T (VU)^T U^T 1, z = A'^T A'^T 1  (A' = A + 1e-4 I)
// ============================================================
__global__ void precompute_kernel(const float* __restrict__ U,
                                  const float* __restrict__ V,
                                  const float* __restrict__ XS,
                                  const float* __restrict__ AT,
                                  const float* __restrict__ XT) {
    int g = blockIdx.x, t = threadIdx.x;
    const float* Ug = U + (size_t)g * nS * RK;
    const float* Vg = V + (size_t)g * RK * nS;
    const float* Ag = AT + (size_t)g * nS * nS;

    __shared__ float VU[RK][RK];
    __shared__ float u1[RK], u2a[RK], u2[RK], sv[nS];

    // diag normalizers: d0 = sqrt(||x||^2 + 1e-4)
    if (t < nS) {
        const float4* row = (const float4*)(XS + (size_t)g * nS * Dd + t * Dd);
        float acc = 0.f;
        #pragma unroll
        for (int k = 0; k < Dd / 4; k++) {
            float4 v = row[k];
            acc += v.x * v.x + v.y * v.y + v.z * v.z + v.w * v.w;
        }
        g_d0S[g][t] = sqrtf(acc + 1e-4f);
    } else if (t < 2 * nS) {
        int r = t - nS;
        const float4* row = (const float4*)(XT + (size_t)g * nS * Dd + r * Dd);
        float acc = 0.f;
        #pragma unroll
        for (int k = 0; k < Dd / 4; k++) {
            float4 v = row[k];
            acc += v.x * v.x + v.y * v.y + v.z * v.z + v.w * v.w;
        }
        g_d0T[g][r] = sqrtf(acc + 1e-4f);
    }

    // VU[i][j] = sum_a V[i,a] U[a,j]   (16x16)
    for (int e = t; e < RK * RK; e += blockDim.x) {
        int i = e / RK, j = e % RK;
        float acc = 0.f;
        for (int a = 0; a < nS; a++) acc += Vg[i * nS + a] * Ug[a * RK + j];
        VU[i][j] = acc;
    }
    __syncthreads();

    // u1 = U^T 1 ;  sv = A'^T 1 (column sums of A, + 1e-4 from diag shift)
    if (t < RK) {
        float acc = 0.f;
        for (int a = 0; a < nS; a++) acc += Ug[a * RK + t];
        u1[t] = acc;
    } else if (t < RK + nS) {
        int i = t - RK;
        float acc = 0.f;
        for (int j = 0; j < nS; j++) acc += Ag[j * nS + i];
        sv[i] = acc + 1e-4f;
    }
    __syncthreads();
    if (t < RK) {  // u2a = VU^T u1
        float acc = 0.f;
        for (int r = 0; r < RK; r++) acc += VU[r][t] * u1[r];
        u2a[t] = acc;
    }
    __syncthreads();
    if (t < RK) {  // u2 = VU^T u2a   ( (VU^2)^T u1 )
        float acc = 0.f;
        for (int r = 0; r < RK; r++) acc += VU[r][t] * u2a[r];
        u2[t] = acc;
    }
    __syncthreads();
    if (t < nS) {  // w = V^T u2
        float acc = 0.f;
        for (int r = 0; r < RK; r++) acc += Vg[r * nS + t] * u2[r];
        g_w[g][t] = acc;
    } else if (t < 2 * nS) {  // z = A'^T sv
        int i = t - nS;
        float acc = 0.f;
        for (int j = 0; j < nS; j++) acc += Ag[j * nS + i] * sv[j];
        g_z[g][i] = acc + 1e-4f * sv[i];
    }
}

// ============================================================
// Kernel B: per (N,M) pair: sigma = X_N X_M^T + 1e-4 (48x48),
// 2-layer arccos NTK recursion, bilinear reduce with (w,w) or (w,z).
// z==0 -> K_SS (symmetric, M>=N only, write both), z==1 -> K_ST.
// ============================================================
__global__ void pair_kernel(const float* __restrict__ XS,
                            const float* __restrict__ XT,
                            float* __restrict__ KSS) {
    int Nn = blockIdx.x, Mm = blockIdx.y, zz = blockIdx.z;
    if (zz == 0 && Mm < Nn) return;

    extern __shared__ float sm[];
    float* XL = sm;                 // 48 x 132
    float* XR = sm + nS * LDX;      // 48 x 132
    float* dL = XR + nS * LDX;
    float* dR = dL + nS;
    float* vL = dR + nS;
    float* vR = vL + nS;

    int t = threadIdx.x;
    const float* XLp = XS + (size_t)Nn * nS * Dd;
    const float* XRp = (zz ? XT : XS) + (size_t)Mm * nS * Dd;

    for (int i = t; i < nS * Dd / 4; i += 256) {
        int row = i >> 5, col = i & 31;
        float4 v = ((const float4*)XLp)[i];
        *((float4*)(XL + row * LDX + col * 4)) = v;
        float4 w = ((const float4*)XRp)[i];
        *((float4*)(XR + row * LDX + col * 4)) = w;
    }
    if (t < nS) {
        dL[t] = g_d0S[Nn][t];
        vL[t] = g_w[Nn][t];
    } else if (t < 2 * nS) {
        int r = t - nS;
        if (zz) { dR[r] = g_d0T[Mm][r]; vR[r] = g_z[Mm][r]; }
        else    { dR[r] = g_d0S[Mm][r]; vR[r] = g_w[Mm][r]; }
    }
    __syncthreads();

    int ty = t >> 4, tx = t & 15;
    float acc[3][3];
    #pragma unroll
    for (int i = 0; i < 3; i++)
        #pragma unroll
        for (int j = 0; j < 3; j++) acc[i][j] = 0.f;

    for (int k = 0; k < Dd; k += 4) {
        float4 l[3], r[3];
        #pragma unroll
        for (int i = 0; i < 3; i++) l[i] = *((const float4*)(XL + (ty + 16 * i) * LDX + k));
        #pragma unroll
        for (int j = 0; j < 3; j++) r[j] = *((const float4*)(XR + (tx + 16 * j) * LDX + k));
        #pragma unroll
        for (int i = 0; i < 3; i++)
            #pragma unroll
            for (int j = 0; j < 3; j++)
                acc[i][j] += l[i].x * r[j].x + l[i].y * r[j].y +
                             l[i].z * r[j].z + l[i].w * r[j].w;
    }

    const float PI_F = 3.14159265358979323846f;
    const float sc = 0.9999f;
    float thc = acosf(sc);
    float c1 = (sc * (PI_F - thc) + sqrtf(1.f - sc * sc)) / PI_F;  // layer-1 diag const

    float partial = 0.f;
    #pragma unroll
    for (int i = 0; i < 3; i++) {
        int a = ty + 16 * i;
        float da = dL[a], wa = vL[a];
        #pragma unroll
        for (int j = 0; j < 3; j++) {
            int b = tx + 16 * j;
            float p = da * dR[b];
            float sigma = acc[i][j] + 1e-4f;
            float ntk = sigma;
            float tmp = p + 1e-6f;
            #pragma unroll
            for (int l = 0; l < 2; l++) {
                float si = sigma / tmp;
                si = fminf(fmaxf(si, -0.9999f), 0.9999f);
                float th = acosf(si);
                float pit = PI_F - th;
                float s = (si * pit + sqrtf(fmaxf(1.f - si * si, 0.f))) / PI_F;
                ntk = ntk * (pit / PI_F) + s;
                sigma = s * tmp;
                tmp = c1 * p + 1e-6f;  // diag[1] = sqrt(c1)*diag[0]
            }
            partial += wa * ntk * vR[b];
        }
    }

    // block reduction
    #pragma unroll
    for (int o = 16; o > 0; o >>= 1)
        partial += __shfl_down_sync(0xffffffffu, partial, o);
    __shared__ float sred[8];
    if ((t & 31) == 0) sred[t >> 5] = partial;
    __syncthreads();
    if (t == 0) {
        float s = 0.f;
        #pragma unroll
        for (int w = 0; w < 8; w++) s += sred[w];
        if (zz == 0) {
            KSS[Nn * Ng + Mm] = s;
            KSS[Mm * Ng + Nn] = s;
        } else {
            g_KST[Nn * Ng + Mm] = s;
        }
    }
}

// ============================================================
// Kernel C: regularize, Gauss-Jordan solve (partial pivoting),
// pred = K_ST^T @ alpha. Single block.
// ============================================================
__global__ void solve_kernel(const float* __restrict__ yS,
                             const float* __restrict__ KSS,
                             float* __restrict__ out) {
    __shared__ float aug[Ng][108];  // [K | y], padded
    __shared__ float bv[128];
    __shared__ int bi[128];
    __shared__ float fct[Ng];
    int t = threadIdx.x;

    for (int idx = t; idx < Ng * Ng; idx += 128)
        aug[idx / Ng][idx % Ng] = KSS[idx];
    for (int idx = t; idx < Ng * Cc; idx += 128)
        aug[idx / Cc][Ng + idx % Cc] = yS[idx];
    __syncthreads();

    // trace -> regularizer
    float tr = 0.f;
    for (int i = t; i < Ng; i += 128) tr += aug[i][i];
    bv[t] = tr;
    __syncthreads();
    for (int o = 64; o > 0; o >>= 1) {
        if (t < o) bv[t] += bv[t + o];
        __syncthreads();
    }
    float reg = 1e-6f * bv[0] / (float)Ng;
    __syncthreads();
    for (int i = t; i < Ng; i += 128) aug[i][i] += reg;
    __syncthreads();

    // Gauss-Jordan with partial pivoting
    for (int k = 0; k < Ng; k++) {
        float best = -1.f;
        int bidx = k;
        for (int i = k + t; i < Ng; i += 128) {
            float a = fabsf(aug[i][k]);
            if (a > best) { best = a; bidx = i; }
        }
        bv[t] = best; bi[t] = bidx;
        __syncthreads();
        for (int o = 64; o > 0; o >>= 1) {
            if (t < o && bv[t + o] > bv[t]) { bv[t] = bv[t + o]; bi[t] = bi[t + o]; }
            __syncthreads();
        }
        int p = bi[0];
        if (p != k) {
            for (int j = t; j < 106; j += 128) {
                float tv = aug[k][j];
                aug[k][j] = aug[p][j];
                aug[p][j] = tv;
            }
        }
        __syncthreads();
        float piv = aug[k][k];
        for (int i = t; i < Ng; i += 128)
            fct[i] = (i == k) ? 0.f : (aug[i][k] / piv);
        __syncthreads();
        int ncol = 106 - k;
        for (int idx = t; idx < Ng * ncol; idx += 128) {
            int i = idx / ncol;
            if (i == k) continue;
            int j = k + (idx - i * ncol);
            aug[i][j] = fmaf(-fct[i], aug[k][j], aug[i][j]);
        }
        __syncthreads();
    }

    // alpha = rhs / diag
    for (int idx = t; idx < Ng * Cc; idx += 128) {
        int i = idx / Cc, c = idx % Cc;
        aug[i][Ng + c] /= aug[i][i];
    }
    __syncthreads();

    // pred[m][c] = sum_N K_ST[N][m] * alpha[N][c]
    for (int idx = t; idx < Ng * Cc; idx += 128) {
        int m = idx / Cc, c = idx % Cc;
        float acc = 0.f;
        for (int n2 = 0; n2 < Ng; n2++)
            acc += g_KST[n2 * Ng + m] * aug[n2][Ng + c];
        out[idx] = acc;  // pred at out[0:960]
    }
}

// ============================================================
extern "C" void kernel_launch(void* const* d_in, const int* in_sizes, int n_in,
                              void* d_out, int out_size) {
    const float* U  = (const float*)d_in[0];  // U_S (96,48,16)
    const float* V  = (const float*)d_in[1];  // V_S (96,16,48)
    const float* XS = (const float*)d_in[2];  // X_S (96,48,128)
    const float* yS = (const float*)d_in[3];  // y_S (96,10)
    const float* AT = (const float*)d_in[4];  // A_T (96,48,48)
    const float* XT = (const float*)d_in[5];  // X_T (96,48,128)
    float* out = (float*)d_out;               // [pred (96,10) | K_SS (96,96)]
    float* KSS = out + Ng * Cc;

    precompute_kernel<<<Ng, 128>>>(U, V, XS, AT, XT);

    const int SMEM = (2 * nS * LDX + 4 * nS) * (int)sizeof(float);  // ~51.5 KB
    cudaFuncSetAttribute(pair_kernel, cudaFuncAttributeMaxDynamicSharedMemorySize, SMEM);
    dim3 grid(Ng, Ng, 2);
    pair_kernel<<<grid, 256, SMEM>>>(XS, XT, KSS);

    solve_kernel<<<1, 128>>>(yS, KSS, out);
}